// round 4
// baseline (speedup 1.0000x reference)
#include <cuda_runtime.h>
#include <cuda_bf16.h>

// Problem shapes (fixed by the dataset):
//   text:        [16, 2048, 256] f32      d_in[0]
//   const_mat:   [16, 2048, 2048] i32     d_in[1]   (UNUSED: softmax rows sum to 1)
//   const_labels:[16, 2048, 8] i32        d_in[2]
//   emb_table:   [100, 128] f32           d_in[3]
//   attn_W:      [256, 384] f32           d_in[4]   (UNUSED: cancels in softmax)
//   attn_b:      [256] f32                d_in[5]   (UNUSED)
//   fc_W:        [256, 128] f32           d_in[6]
//   fc_b:        [256] f32                d_in[7]
//   out:         [16, 2048, 256] f32
//
// Collapse: out[pos,d] = relu( text[pos,d] + sum_{k=0..7} G[labels[pos,k], d] )
// with G[n,d] = 0.125 * (fc_b[d] + emb_table[n] . fc_W[d]).
//
// R4: dual-pipe gather. G lives BOTH in smem (full 100 KB copy per CTA) and in
// L1 (global table). 5 of 8 gathers go through the smem crossbar (128 B/cyc),
// 3 + text/out/labels through L1tex (128 B/cyc) -> each pipe carries ~half of
// what L1 alone carried in R2/R3.

#define CN    100
#define CD    128
#define DIM   256
#define KLBL  8
#define D4    (DIM / 4)

#define FG_BLOCK 512
#define FG_GRID  296            // 2 CTAs per SM (148 SMs)

__device__ float g_G[CN * DIM];  // 100 KB precomputed table

// ---------------------------------------------------------------------------
// Kernel A: G[n,d] = 0.125 * (fc_b[d] + sum_c emb_table[n,c] * fc_W[d,c])
// ---------------------------------------------------------------------------
__global__ void __launch_bounds__(DIM) build_G_kernel(
    const float* __restrict__ emb_table,
    const float* __restrict__ fc_W,
    const float* __restrict__ fc_b)
{
    __shared__ float se[CD];
    const int n = blockIdx.x;
    const int d = threadIdx.x;
    if (d < CD) se[d] = emb_table[n * CD + d];
    __syncthreads();

    const float4* w4 = reinterpret_cast<const float4*>(fc_W + d * CD);
    float acc = fc_b[d];
    #pragma unroll
    for (int c4 = 0; c4 < CD / 4; c4++) {
        float4 w = w4[c4];
        acc = fmaf(se[c4 * 4 + 0], w.x, acc);
        acc = fmaf(se[c4 * 4 + 1], w.y, acc);
        acc = fmaf(se[c4 * 4 + 2], w.z, acc);
        acc = fmaf(se[c4 * 4 + 3], w.w, acc);
    }
    g_G[n * DIM + d] = 0.125f * acc;
}

// ---------------------------------------------------------------------------
// Kernel B: fused gather-add-relu, split across smem crossbar + L1tex.
// ---------------------------------------------------------------------------
__global__ void __launch_bounds__(FG_BLOCK, 2) fused_gather_kernel(
    const float4* __restrict__ text4,
    const int*    __restrict__ labels,
    float4*       __restrict__ out4,
    int n4total)
{
    extern __shared__ float4 sG4[];   // 6400 float4 = 100 KB

    const float4* __restrict__ G4 = reinterpret_cast<const float4*>(g_G);

    // Stage G into shared memory (coalesced float4 copies).
    #pragma unroll
    for (int i = threadIdx.x; i < (CN * DIM) / 4; i += FG_BLOCK)
        sG4[i] = G4[i];
    __syncthreads();

    const int stride = FG_GRID * FG_BLOCK;  // 151552

    for (int idx = blockIdx.x * FG_BLOCK + threadIdx.x; idx < n4total; idx += stride) {
        const int pos = idx >> 6;         // warp-uniform
        const int d4  = idx & (D4 - 1);

        const int4* lb = reinterpret_cast<const int4*>(labels) + (pos << 1);
        const int4 l0 = __ldg(lb + 0);
        const int4 l1 = __ldg(lb + 1);

        // Streaming text read (evict-first: keep G resident in L1).
        const float4 t = __ldcs(text4 + idx);

        // 5 gathers via shared-memory crossbar (conflict-free: uniform row,
        // consecutive d4 within the warp).
        const float4 g0 = sG4[(l0.x << 6) + d4];
        const float4 g1 = sG4[(l0.y << 6) + d4];
        const float4 g2 = sG4[(l0.z << 6) + d4];
        const float4 g3 = sG4[(l0.w << 6) + d4];
        const float4 g4 = sG4[(l1.x << 6) + d4];

        // 3 gathers via L1 (global table stays hot in L1).
        const float4 g5 = __ldg(G4 + ((l1.y << 6) + d4));
        const float4 g6 = __ldg(G4 + ((l1.z << 6) + d4));
        const float4 g7 = __ldg(G4 + ((l1.w << 6) + d4));

        float4 r;
        r.x = fmaxf(t.x + ((g0.x + g1.x) + (g2.x + g3.x)) + ((g4.x + g5.x) + (g6.x + g7.x)), 0.0f);
        r.y = fmaxf(t.y + ((g0.y + g1.y) + (g2.y + g3.y)) + ((g4.y + g5.y) + (g6.y + g7.y)), 0.0f);
        r.z = fmaxf(t.z + ((g0.z + g1.z) + (g2.z + g3.z)) + ((g4.z + g5.z) + (g6.z + g7.z)), 0.0f);
        r.w = fmaxf(t.w + ((g0.w + g1.w) + (g2.w + g3.w)) + ((g4.w + g5.w) + (g6.w + g7.w)), 0.0f);

        __stcs(out4 + idx, r);
    }
}

// ---------------------------------------------------------------------------
extern "C" void kernel_launch(void* const* d_in, const int* in_sizes, int n_in,
                              void* d_out, int out_size)
{
    const float* text      = (const float*)d_in[0];
    const int*   labels    = (const int*)  d_in[2];
    const float* emb_table = (const float*)d_in[3];
    const float* fc_W      = (const float*)d_in[6];
    const float* fc_b      = (const float*)d_in[7];
    float*       out       = (float*)d_out;

    const int n4total = in_sizes[0] / 4;  // 2,097,152

    const int smemBytes = CN * DIM * (int)sizeof(float);  // 102400
    cudaFuncSetAttribute(fused_gather_kernel,
                         cudaFuncAttributeMaxDynamicSharedMemorySize, smemBytes);

    build_G_kernel<<<CN, DIM>>>(emb_table, fc_W, fc_b);
    fused_gather_kernel<<<FG_GRID, FG_BLOCK, smemBytes>>>(
        reinterpret_cast<const float4*>(text),
        labels,
        reinterpret_cast<float4*>(out),
        n4total);
}

// round 5
// speedup vs baseline: 1.3725x; 1.3725x over previous
#include <cuda_runtime.h>
#include <cuda_fp16.h>
#include <cuda_bf16.h>

// Problem shapes (fixed by the dataset):
//   text:        [16, 2048, 256] f32      d_in[0]
//   const_mat:   [16, 2048, 2048] i32     d_in[1]   (UNUSED: softmax rows sum to 1)
//   const_labels:[16, 2048, 8] i32        d_in[2]
//   emb_table:   [100, 128] f32           d_in[3]
//   attn_W:      [256, 384] f32           d_in[4]   (UNUSED: cancels in softmax)
//   attn_b:      [256] f32                d_in[5]   (UNUSED)
//   fc_W:        [256, 128] f32           d_in[6]
//   fc_b:        [256] f32                d_in[7]
//   out:         [16, 2048, 256] f32
//
// Collapse: out[pos,d] = relu( text[pos,d] + sum_{k=0..7} G[labels[pos,k], d] )
// with G[n,d] = 0.125 * (fc_b[d] + emb_table[n] . fc_W[d]).
//
// R5: G stored as fp16 (50 KB, L1-resident). Gathers become LDG.64 -> half the
// wavefronts AND half the within-LDG replay exposure (the measured 2.07 cyc/wf
// limit on multi-line LDGs). One HADD2 pre-reduction, fp32 accumulation.

#define CN    100
#define CD    128
#define DIM   256
#define KLBL  8
#define D4    (DIM / 4)

__device__ __half g_Gh[CN * DIM];  // 50 KB fp16 table

// ---------------------------------------------------------------------------
// Kernel A: G[n,d] = 0.125 * (fc_b[d] + sum_c emb_table[n,c] * fc_W[d,c]) -> fp16
// ---------------------------------------------------------------------------
__global__ void __launch_bounds__(DIM) build_G_kernel(
    const float* __restrict__ emb_table,
    const float* __restrict__ fc_W,
    const float* __restrict__ fc_b)
{
    __shared__ float se[CD];
    const int n = blockIdx.x;
    const int d = threadIdx.x;
    if (d < CD) se[d] = emb_table[n * CD + d];
    __syncthreads();

    const float4* w4 = reinterpret_cast<const float4*>(fc_W + d * CD);
    float acc = fc_b[d];
    #pragma unroll
    for (int c4 = 0; c4 < CD / 4; c4++) {
        float4 w = w4[c4];
        acc = fmaf(se[c4 * 4 + 0], w.x, acc);
        acc = fmaf(se[c4 * 4 + 1], w.y, acc);
        acc = fmaf(se[c4 * 4 + 2], w.z, acc);
        acc = fmaf(se[c4 * 4 + 3], w.w, acc);
    }
    g_Gh[n * DIM + d] = __float2half_rn(0.125f * acc);
}

// ---------------------------------------------------------------------------
// Kernel B: fused gather-add-relu. One thread per output float4.
// Gathers are uint2 (= 4 halves = LDG.64). pos is warp-uniform.
// ---------------------------------------------------------------------------
__device__ __forceinline__ __half2 as_h2(unsigned u) {
    return *reinterpret_cast<const __half2*>(&u);
}

__global__ void __launch_bounds__(256) fused_gather_kernel(
    const float4* __restrict__ text4,
    const int*    __restrict__ labels,
    float4*       __restrict__ out4,
    int n4total)
{
    const int gid = blockIdx.x * blockDim.x + threadIdx.x;
    if (gid >= n4total) return;

    const int pos = gid >> 6;        // warp-uniform
    const int d4  = gid & (D4 - 1);  // uint2 index within the row (64 per row)

    const int4* lb = reinterpret_cast<const int4*>(labels) + (pos << 1);
    const int4 l0 = __ldg(lb + 0);
    const int4 l1 = __ldg(lb + 1);

    const uint2* __restrict__ Gh = reinterpret_cast<const uint2*>(g_Gh);

    // 9 independent loads up front for MLP.
    const float4 t  = __ldcs(text4 + gid);
    const uint2 u0 = __ldg(Gh + ((l0.x << 6) + d4));
    const uint2 u1 = __ldg(Gh + ((l0.y << 6) + d4));
    const uint2 u2 = __ldg(Gh + ((l0.z << 6) + d4));
    const uint2 u3 = __ldg(Gh + ((l0.w << 6) + d4));
    const uint2 u4 = __ldg(Gh + ((l1.x << 6) + d4));
    const uint2 u5 = __ldg(Gh + ((l1.y << 6) + d4));
    const uint2 u6 = __ldg(Gh + ((l1.z << 6) + d4));
    const uint2 u7 = __ldg(Gh + ((l1.w << 6) + d4));

    // One pairwise HADD2 level in fp16 (small operands, tiny rounding error),
    // then convert to fp32 and finish the reduction exactly.
    const __half2 p0lo = __hadd2(as_h2(u0.x), as_h2(u1.x));
    const __half2 p0hi = __hadd2(as_h2(u0.y), as_h2(u1.y));
    const __half2 p1lo = __hadd2(as_h2(u2.x), as_h2(u3.x));
    const __half2 p1hi = __hadd2(as_h2(u2.y), as_h2(u3.y));
    const __half2 p2lo = __hadd2(as_h2(u4.x), as_h2(u5.x));
    const __half2 p2hi = __hadd2(as_h2(u4.y), as_h2(u5.y));
    const __half2 p3lo = __hadd2(as_h2(u6.x), as_h2(u7.x));
    const __half2 p3hi = __hadd2(as_h2(u6.y), as_h2(u7.y));

    const float2 f0lo = __half22float2(p0lo);
    const float2 f1lo = __half22float2(p1lo);
    const float2 f2lo = __half22float2(p2lo);
    const float2 f3lo = __half22float2(p3lo);
    const float2 f0hi = __half22float2(p0hi);
    const float2 f1hi = __half22float2(p1hi);
    const float2 f2hi = __half22float2(p2hi);
    const float2 f3hi = __half22float2(p3hi);

    const float slo_x = (f0lo.x + f1lo.x) + (f2lo.x + f3lo.x);
    const float slo_y = (f0lo.y + f1lo.y) + (f2lo.y + f3lo.y);
    const float shi_x = (f0hi.x + f1hi.x) + (f2hi.x + f3hi.x);
    const float shi_y = (f0hi.y + f1hi.y) + (f2hi.y + f3hi.y);

    float4 r;
    r.x = fmaxf(t.x + slo_x, 0.0f);
    r.y = fmaxf(t.y + slo_y, 0.0f);
    r.z = fmaxf(t.z + shi_x, 0.0f);
    r.w = fmaxf(t.w + shi_y, 0.0f);

    __stcs(out4 + gid, r);
}

// ---------------------------------------------------------------------------
extern "C" void kernel_launch(void* const* d_in, const int* in_sizes, int n_in,
                              void* d_out, int out_size)
{
    const float* text      = (const float*)d_in[0];
    const int*   labels    = (const int*)  d_in[2];
    const float* emb_table = (const float*)d_in[3];
    const float* fc_W      = (const float*)d_in[6];
    const float* fc_b      = (const float*)d_in[7];
    float*       out       = (float*)d_out;

    const int ntotal  = in_sizes[0];   // 8,388,608
    const int n4total = ntotal / 4;    // 2,097,152

    build_G_kernel<<<CN, DIM>>>(emb_table, fc_W, fc_b);

    const int block = 256;
    const int grid  = (n4total + block - 1) / block;   // 8192
    fused_gather_kernel<<<grid, block>>>(
        reinterpret_cast<const float4*>(text),
        labels,
        reinterpret_cast<float4*>(out),
        n4total);
}

// round 6
// speedup vs baseline: 1.5398x; 1.1218x over previous
#include <cuda_runtime.h>
#include <cuda_fp16.h>
#include <cuda_bf16.h>

// Problem shapes (fixed by the dataset):
//   text:        [16, 2048, 256] f32      d_in[0]
//   const_mat:   [16, 2048, 2048] i32     d_in[1]   (UNUSED: softmax rows sum to 1)
//   const_labels:[16, 2048, 8] i32        d_in[2]
//   emb_table:   [100, 128] f32           d_in[3]
//   attn_W:      [256, 384] f32           d_in[4]   (UNUSED: cancels in softmax)
//   attn_b:      [256] f32                d_in[5]   (UNUSED)
//   fc_W:        [256, 128] f32           d_in[6]
//   fc_b:        [256] f32                d_in[7]
//   out:         [16, 2048, 256] f32
//
// Collapse: out[pos,d] = relu( text[pos,d] + sum_{k=0..7} G[labels[pos,k], d] )
// with G[n,d] = 0.125 * (fc_b[d] + emb_table[n] . fc_W[d]), G stored fp16.
//
// R6: latency-exposure attack. One warp = one position; each thread makes the
// float4s at d4 and d4+32 of that row. 16 independent uint2 gathers + 2 text
// loads + 2 label loads batched per thread -> 2x outstanding loads vs R5,
// amortized label traffic, shared gather bases.

#define CN    100
#define CD    128
#define DIM   256
#define KLBL  8

__device__ __half g_Gh[CN * DIM];  // 50 KB fp16 table

// ---------------------------------------------------------------------------
// Kernel A: G[n,d] = 0.125 * (fc_b[d] + sum_c emb_table[n,c] * fc_W[d,c]) -> fp16
// ---------------------------------------------------------------------------
__global__ void __launch_bounds__(DIM) build_G_kernel(
    const float* __restrict__ emb_table,
    const float* __restrict__ fc_W,
    const float* __restrict__ fc_b)
{
    __shared__ float se[CD];
    const int n = blockIdx.x;
    const int d = threadIdx.x;
    if (d < CD) se[d] = emb_table[n * CD + d];
    __syncthreads();

    const float4* w4 = reinterpret_cast<const float4*>(fc_W + d * CD);
    float acc = fc_b[d];
    #pragma unroll
    for (int c4 = 0; c4 < CD / 4; c4++) {
        float4 w = w4[c4];
        acc = fmaf(se[c4 * 4 + 0], w.x, acc);
        acc = fmaf(se[c4 * 4 + 1], w.y, acc);
        acc = fmaf(se[c4 * 4 + 2], w.z, acc);
        acc = fmaf(se[c4 * 4 + 3], w.w, acc);
    }
    g_Gh[n * DIM + d] = __float2half_rn(0.125f * acc);
}

// ---------------------------------------------------------------------------
// Kernel B: fused gather-add-relu. gid -> pos = gid>>5, d4 = gid&31.
// Thread covers output float4s (pos, d4) and (pos, d4+32).
// ---------------------------------------------------------------------------
__device__ __forceinline__ __half2 as_h2(unsigned u) {
    return *reinterpret_cast<const __half2*>(&u);
}

__device__ __forceinline__ float4 reduce8(
    const uint2& u0, const uint2& u1, const uint2& u2, const uint2& u3,
    const uint2& u4, const uint2& u5, const uint2& u6, const uint2& u7,
    const float4& t)
{
    // One HADD2 level in fp16, then fp32 finish.
    const __half2 p0lo = __hadd2(as_h2(u0.x), as_h2(u1.x));
    const __half2 p0hi = __hadd2(as_h2(u0.y), as_h2(u1.y));
    const __half2 p1lo = __hadd2(as_h2(u2.x), as_h2(u3.x));
    const __half2 p1hi = __hadd2(as_h2(u2.y), as_h2(u3.y));
    const __half2 p2lo = __hadd2(as_h2(u4.x), as_h2(u5.x));
    const __half2 p2hi = __hadd2(as_h2(u4.y), as_h2(u5.y));
    const __half2 p3lo = __hadd2(as_h2(u6.x), as_h2(u7.x));
    const __half2 p3hi = __hadd2(as_h2(u6.y), as_h2(u7.y));

    const float2 f0lo = __half22float2(p0lo);
    const float2 f1lo = __half22float2(p1lo);
    const float2 f2lo = __half22float2(p2lo);
    const float2 f3lo = __half22float2(p3lo);
    const float2 f0hi = __half22float2(p0hi);
    const float2 f1hi = __half22float2(p1hi);
    const float2 f2hi = __half22float2(p2hi);
    const float2 f3hi = __half22float2(p3hi);

    float4 r;
    r.x = fmaxf(t.x + (f0lo.x + f1lo.x) + (f2lo.x + f3lo.x), 0.0f);
    r.y = fmaxf(t.y + (f0lo.y + f1lo.y) + (f2lo.y + f3lo.y), 0.0f);
    r.z = fmaxf(t.z + (f0hi.x + f1hi.x) + (f2hi.x + f3hi.x), 0.0f);
    r.w = fmaxf(t.w + (f0hi.y + f1hi.y) + (f2hi.y + f3hi.y), 0.0f);
    return r;
}

__global__ void __launch_bounds__(256, 4) fused_gather_kernel(
    const float4* __restrict__ text4,
    const int*    __restrict__ labels,
    float4*       __restrict__ out4,
    int nhalf)   // number of (pos, d4<32) slots = npos*32
{
    const int gid = blockIdx.x * blockDim.x + threadIdx.x;
    if (gid >= nhalf) return;

    const int pos = gid >> 5;        // warp-uniform (warp = one position)
    const int d4  = gid & 31;        // uint2 slot 0..31; twin at d4+32

    const int4* lb = reinterpret_cast<const int4*>(labels) + (pos << 1);
    const int4 l0 = __ldg(lb + 0);
    const int4 l1 = __ldg(lb + 1);

    const uint2* __restrict__ Gh = reinterpret_cast<const uint2*>(g_Gh);

    const int idxA = (pos << 6) + d4;        // output float4 index, low half
    const int idxB = idxA + 32;              // high half

    // Batch all independent loads.
    const float4 tA = __ldcs(text4 + idxA);
    const float4 tB = __ldcs(text4 + idxB);

    const int b0 = (l0.x << 6) + d4;
    const int b1 = (l0.y << 6) + d4;
    const int b2 = (l0.z << 6) + d4;
    const int b3 = (l0.w << 6) + d4;
    const int b4 = (l1.x << 6) + d4;
    const int b5 = (l1.y << 6) + d4;
    const int b6 = (l1.z << 6) + d4;
    const int b7 = (l1.w << 6) + d4;

    const uint2 a0 = __ldg(Gh + b0);
    const uint2 a1 = __ldg(Gh + b1);
    const uint2 a2 = __ldg(Gh + b2);
    const uint2 a3 = __ldg(Gh + b3);
    const uint2 a4 = __ldg(Gh + b4);
    const uint2 a5 = __ldg(Gh + b5);
    const uint2 a6 = __ldg(Gh + b6);
    const uint2 a7 = __ldg(Gh + b7);

    const uint2 c0 = __ldg(Gh + b0 + 32);
    const uint2 c1 = __ldg(Gh + b1 + 32);
    const uint2 c2 = __ldg(Gh + b2 + 32);
    const uint2 c3 = __ldg(Gh + b3 + 32);
    const uint2 c4 = __ldg(Gh + b4 + 32);
    const uint2 c5 = __ldg(Gh + b5 + 32);
    const uint2 c6 = __ldg(Gh + b6 + 32);
    const uint2 c7 = __ldg(Gh + b7 + 32);

    const float4 rA = reduce8(a0, a1, a2, a3, a4, a5, a6, a7, tA);
    const float4 rB = reduce8(c0, c1, c2, c3, c4, c5, c6, c7, tB);

    __stcs(out4 + idxA, rA);
    __stcs(out4 + idxB, rB);
}

// ---------------------------------------------------------------------------
extern "C" void kernel_launch(void* const* d_in, const int* in_sizes, int n_in,
                              void* d_out, int out_size)
{
    const float* text      = (const float*)d_in[0];
    const int*   labels    = (const int*)  d_in[2];
    const float* emb_table = (const float*)d_in[3];
    const float* fc_W      = (const float*)d_in[6];
    const float* fc_b      = (const float*)d_in[7];
    float*       out       = (float*)d_out;

    const int ntotal = in_sizes[0];        // 8,388,608
    const int nhalf  = ntotal / 8;         // 1,048,576 threads (2 float4 each)

    build_G_kernel<<<CN, DIM>>>(emb_table, fc_W, fc_b);

    const int block = 256;
    const int grid  = (nhalf + block - 1) / block;   // 4096
    fused_gather_kernel<<<grid, block>>>(
        reinterpret_cast<const float4*>(text),
        labels,
        reinterpret_cast<float4*>(out),
        nhalf);
}